// round 3
// baseline (speedup 1.0000x reference)
#include <cuda_runtime.h>
#include <math.h>
#include <stdint.h>

// DPLSTMCell row-0: out[n] = LSTM epilogue over 8 dot-products (4 gates x {Wih,Whh}).
// R3: weight stream via TMA bulk copy (cp.async.bulk.shared::cta.global) -> smem,
// because one-shot LDG bursts cap at ~3.5TB/s (per-SM outstanding-line limit).
// 8 rows x 4KB = 32KB smem per block; 7 blocks/SM -> 1036 resident blocks = single wave.

#define H 1024
#define D 1024

__device__ __forceinline__ float warp_reduce(float v) {
    #pragma unroll
    for (int off = 16; off > 0; off >>= 1)
        v += __shfl_xor_sync(0xFFFFFFFFu, v, off);
    return v;
}

__device__ __forceinline__ uint32_t smem_u32(const void* p) {
    return (uint32_t)__cvta_generic_to_shared(p);
}

__global__ __launch_bounds__(256, 7)
void lstm_row0_tma_kernel(const float* __restrict__ x,
                          const float* __restrict__ h,
                          const float* __restrict__ c_prev,
                          const float* __restrict__ Wih,
                          const float* __restrict__ Whh,
                          const float* __restrict__ bih,
                          const float* __restrict__ bhh,
                          float* __restrict__ out) {
    // 8 weight rows of 1024 floats each (32KB), + mbarrier + partial sums.
    __shared__ __align__(128) float swt[8][D];
    __shared__ __align__(8) uint64_t mbar;
    __shared__ float sums[8];

    const int n    = blockIdx.x;
    const int tid  = threadIdx.x;
    const int wid  = tid >> 5;            // 0..7
    const int lane = tid & 31;

    const uint32_t mbar_a = smem_u32(&mbar);

    if (tid == 0) {
        asm volatile("mbarrier.init.shared.b64 [%0], 1;" :: "r"(mbar_a) : "memory");
    }
    __syncthreads();

    if (tid == 0) {
        asm volatile("mbarrier.arrive.expect_tx.shared.b64 _, [%0], %1;"
                     :: "r"(mbar_a), "r"(8 * D * 4) : "memory");
        // Issue 8 bulk copies: row r = gate*2+mat  ->  W[gate*H+n] (4KB each).
        #pragma unroll
        for (int r = 0; r < 8; r++) {
            const int gate = r >> 1;
            const int mat  = r & 1;
            const float* src = (mat ? Whh : Wih) + (size_t)(gate * H + n) * D;
            const uint32_t dst = smem_u32(&swt[r][0]);
            asm volatile(
                "cp.async.bulk.shared::cta.global.mbarrier::complete_tx::bytes "
                "[%0], [%1], %2, [%3];"
                :: "r"(dst), "l"(src), "n"(D * 4), "r"(mbar_a) : "memory");
        }
    }

    // Wait for the 32KB to land (phase 0).
    {
        uint32_t done;
        asm volatile(
            "{\n\t.reg .pred p;\n\t"
            "mbarrier.try_wait.parity.acquire.cta.shared::cta.b64 p, [%1], 0;\n\t"
            "selp.b32 %0, 1, 0, p;\n\t}"
            : "=r"(done) : "r"(mbar_a) : "memory");
        if (!done) {
            asm volatile(
                "{\n\t.reg .pred P1;\n\t"
                "W0_%=:\n\t"
                "mbarrier.try_wait.parity.acquire.cta.shared::cta.b64 P1, [%0], 0, 0x989680;\n\t"
                "@P1 bra.uni WD_%=;\n\t"
                "bra.uni W0_%=;\n\t"
                "WD_%=:\n\t}"
                :: "r"(mbar_a) : "memory");
        }
    }

    // Each warp: dot(smem row wid, vector) with vector from L1/L2 (hot, 8KB total).
    const int mat = wid & 1;
    const float4* __restrict__ v4 =
        reinterpret_cast<const float4*>(mat ? h : x);
    const float4* w4 = reinterpret_cast<const float4*>(&swt[wid][0]);

    float acc = 0.0f;
    #pragma unroll
    for (int i = 0; i < 8; i++) {
        const int idx = lane + i * 32;
        float4 wv = w4[idx];
        float4 xv = __ldg(&v4[idx]);
        acc += wv.x * xv.x + wv.y * xv.y + wv.z * xv.z + wv.w * xv.w;
    }
    acc = warp_reduce(acc);

    if (lane == 0) sums[wid] = acc;
    __syncthreads();

    if (tid == 0) {
        float gi = sums[0] + sums[1] + bih[n]         + bhh[n];
        float gf = sums[2] + sums[3] + bih[H + n]     + bhh[H + n];
        float gg = sums[4] + sums[5] + bih[2 * H + n] + bhh[2 * H + n];
        float go = sums[6] + sums[7] + bih[3 * H + n] + bhh[3 * H + n];

        float i_t = 1.0f / (1.0f + expf(-gi));
        float f_t = 1.0f / (1.0f + expf(-gf));
        float g_t = tanhf(gg);
        float o_t = 1.0f / (1.0f + expf(-go));

        float c_t = f_t * c_prev[n] + i_t * g_t;
        out[n] = o_t * tanhf(c_t);
    }
}

extern "C" void kernel_launch(void* const* d_in, const int* in_sizes, int n_in,
                              void* d_out, int out_size) {
    const float* x      = (const float*)d_in[0];
    const float* h      = (const float*)d_in[1];
    const float* c_prev = (const float*)d_in[2];
    const float* Wih    = (const float*)d_in[3];
    const float* Whh    = (const float*)d_in[4];
    const float* bih    = (const float*)d_in[5];
    const float* bhh    = (const float*)d_in[6];
    float* out = (float*)d_out;

    lstm_row0_tma_kernel<<<H, 256>>>(x, h, c_prev, Wih, Whh, bih, bhh, out);
}